// round 5
// baseline (speedup 1.0000x reference)
#include <cuda_runtime.h>
#include <cuda_bf16.h>
#include <cstdint>

// ---------------------------------------------------------------------------
// Model constants
// ---------------------------------------------------------------------------
#define BATCH     8
#define SEQ       512
#define INPUT_DIM 32
#define DMODEL    256
#define NLAYERS   4
#define DSTATE    16
#define DCONV     4
#define DINNER    512
#define DTRANK    16
#define MROWS     (BATCH*SEQ)    // 4096
#define LN_EPS    1e-5f

// ---------------------------------------------------------------------------
// Device scratch
// ---------------------------------------------------------------------------
__device__ float g_h   [MROWS * DMODEL];
__device__ float g_xn  [MROWS * DMODEL];
__device__ float g_xz  [MROWS * 2 * DINNER];
__device__ float g_u   [MROWS * DINNER];
__device__ float g_dbl [MROWS * 48];
__device__ float g_dt  [MROWS * DINNER];
__device__ float g_y   [MROWS * DINNER];
__device__ float g_t1  [BATCH * DMODEL];
__device__ float g_part[2 * MROWS * DMODEL];   // split-K partials

// ---------------------------------------------------------------------------
// packed f32x2 helpers (Blackwell 2x-rate fp32; PTX-only)
// ---------------------------------------------------------------------------
typedef unsigned long long ull;

__device__ __forceinline__ ull pk2(float x) {
    ull r;
    asm("mov.b64 %0, {%1, %1};" : "=l"(r) : "f"(x));
    return r;
}
__device__ __forceinline__ ull fma2(ull a, ull b, ull c) {
    ull d;
    asm("fma.rn.f32x2 %0, %1, %2, %3;" : "=l"(d) : "l"(a), "l"(b), "l"(c));
    return d;
}
__device__ __forceinline__ float2 upk(ull v) {
    float2 f;
    asm("mov.b64 {%0, %1}, %2;" : "=f"(f.x), "=f"(f.y) : "l"(v));
    return f;
}

// ---------------------------------------------------------------------------
// f32x2 NT GEMM: C[m,n] = sum_k A[m,k] * W[n,k]  (+bias, act)
// CTA tile 128x128, BK=16, 256 threads, 8x8 per-thread (32 fma.f32x2 / k).
// Double-buffered SMEM, reg prefetch, one sync per k-tile.
// Split-K via blockIdx.z: k-slice [z*Klen,(z+1)*Klen), C += z*zstride.
// Requirements: M % 128 == 0, Klen % 16 == 0, N even.
// act: 0 none, 1 softplus
// ---------------------------------------------------------------------------
#define GBM 128
#define GBN 128
#define GBK 16
#define GLD 132   // row stride (floats): 132*4 B, 16B-aligned rows

__global__ __launch_bounds__(256)
void gemm_f2(const float* __restrict__ A, int lda,
             const float* __restrict__ W, int ldw,
             const float* __restrict__ bias,
             float* __restrict__ C, int ldc, size_t zstride,
             int N, int Klen, int act)
{
    __shared__ float As[2][GBK][GLD];
    __shared__ float Ws[2][GBK][GLD];

    const int tid  = threadIdx.x;
    const int tx   = tid & 15;          // N dir
    const int ty   = tid >> 4;          // M dir
    const int row0 = blockIdx.y * GBM;
    const int col0 = blockIdx.x * GBN;
    const int kofs = blockIdx.z * Klen;
    C += (size_t)blockIdx.z * zstride;

    const int lr = tid >> 1;            // 0..127 (tile row for loads)
    const int lk = (tid & 1) * 8;       // 0 / 8
    const bool wvalid = (col0 + lr) < N;

    const int ntiles = Klen / GBK;

    // ---- prologue: tile 0 ----
    float4 av0, av1, wv0, wv1;
    {
        const float* Ap = A + (size_t)(row0 + lr) * lda + kofs + lk;
        av0 = ((const float4*)Ap)[0];
        av1 = ((const float4*)Ap)[1];
        const float* Wp = W + (size_t)(col0 + lr) * ldw + kofs + lk;
        wv0 = wvalid ? ((const float4*)Wp)[0] : make_float4(0.f,0.f,0.f,0.f);
        wv1 = wvalid ? ((const float4*)Wp)[1] : make_float4(0.f,0.f,0.f,0.f);
    }
#pragma unroll
    for (int c = 0; c < 4; c++) {
        As[0][lk + c][lr]     = (&av0.x)[c];
        As[0][lk + 4 + c][lr] = (&av1.x)[c];
        Ws[0][lk + c][lr]     = (&wv0.x)[c];
        Ws[0][lk + 4 + c][lr] = (&wv1.x)[c];
    }
    __syncthreads();

    ull acc[8][4];
#pragma unroll
    for (int i = 0; i < 8; i++)
#pragma unroll
        for (int j = 0; j < 4; j++) acc[i][j] = 0ull;

    for (int t = 0; t < ntiles; t++) {
        const int cur = t & 1;

        // prefetch next tile
        if (t + 1 < ntiles) {
            const float* Ap = A + (size_t)(row0 + lr) * lda + kofs + (t+1)*GBK + lk;
            av0 = ((const float4*)Ap)[0];
            av1 = ((const float4*)Ap)[1];
            const float* Wp = W + (size_t)(col0 + lr) * ldw + kofs + (t+1)*GBK + lk;
            wv0 = wvalid ? ((const float4*)Wp)[0] : make_float4(0.f,0.f,0.f,0.f);
            wv1 = wvalid ? ((const float4*)Wp)[1] : make_float4(0.f,0.f,0.f,0.f);
        }

        // compute current tile
#pragma unroll
        for (int kk = 0; kk < GBK; kk++) {
            float4 a01 = *(const float4*)&As[cur][kk][ty * 8];
            float4 a23 = *(const float4*)&As[cur][kk][ty * 8 + 4];
            ulonglong2 w01 = *(const ulonglong2*)&Ws[cur][kk][tx * 8];
            ulonglong2 w23 = *(const ulonglong2*)&Ws[cur][kk][tx * 8 + 4];

            ull a2[8];
            a2[0] = pk2(a01.x); a2[1] = pk2(a01.y);
            a2[2] = pk2(a01.z); a2[3] = pk2(a01.w);
            a2[4] = pk2(a23.x); a2[5] = pk2(a23.y);
            a2[6] = pk2(a23.z); a2[7] = pk2(a23.w);
            ull w2[4] = {w01.x, w01.y, w23.x, w23.y};

#pragma unroll
            for (int i = 0; i < 8; i++)
#pragma unroll
                for (int j = 0; j < 4; j++)
                    acc[i][j] = fma2(a2[i], w2[j], acc[i][j]);
        }

        // store next tile (other buffer), then fence
        if (t + 1 < ntiles) {
            const int nxt = cur ^ 1;
#pragma unroll
            for (int c = 0; c < 4; c++) {
                As[nxt][lk + c][lr]     = (&av0.x)[c];
                As[nxt][lk + 4 + c][lr] = (&av1.x)[c];
                Ws[nxt][lk + c][lr]     = (&wv0.x)[c];
                Ws[nxt][lk + 4 + c][lr] = (&wv1.x)[c];
            }
            __syncthreads();
        }
    }

    // ---- epilogue ----
#pragma unroll
    for (int i = 0; i < 8; i++) {
        const int r = row0 + ty * 8 + i;
        float* Crow = C + (size_t)r * ldc;
#pragma unroll
        for (int j = 0; j < 4; j++) {
            const int col = col0 + tx * 8 + 2 * j;
            if (col < N) {   // N is even: col,col+1 valid together
                float2 v = upk(acc[i][j]);
                if (bias) { v.x += bias[col]; v.y += bias[col + 1]; }
                if (act == 1) {
                    v.x = (v.x > 20.f) ? v.x : log1pf(__expf(v.x));
                    v.y = (v.y > 20.f) ? v.y : log1pf(__expf(v.y));
                }
                *(float2*)(Crow + col) = v;
            }
        }
    }
}

// ---------------------------------------------------------------------------
// Split-K reduce: out[i] = (resid?resid[i]:0) + sum_z part[z*zstride + i]
// ---------------------------------------------------------------------------
__global__ __launch_bounds__(256)
void reduce_kernel(const float* __restrict__ part, size_t zstride, int nz,
                   const float* __restrict__ resid,
                   float* __restrict__ out, int n)
{
    int i = (blockIdx.x * blockDim.x + threadIdx.x) * 4;
    if (i >= n) return;
    float4 s = resid ? *(const float4*)(resid + i) : make_float4(0.f,0.f,0.f,0.f);
    for (int zi = 0; zi < nz; zi++) {
        float4 p = *(const float4*)(part + (size_t)zi * zstride + i);
        s.x += p.x; s.y += p.y; s.z += p.z; s.w += p.w;
    }
    *(float4*)(out + i) = s;
}

// ---------------------------------------------------------------------------
// LayerNorm: one warp per row of 256
// ---------------------------------------------------------------------------
__global__ __launch_bounds__(256)
void ln_kernel(const float* __restrict__ h,
               const float* __restrict__ w, const float* __restrict__ b,
               float* __restrict__ out)
{
    int row  = blockIdx.x * 8 + (threadIdx.x >> 5);
    int lane = threadIdx.x & 31;
    const float* x = h + (size_t)row * DMODEL;

    float v[8];
    float s = 0.f, ss = 0.f;
#pragma unroll
    for (int i = 0; i < 8; i++) {
        v[i] = x[lane + i * 32];
        s  += v[i];
        ss += v[i] * v[i];
    }
#pragma unroll
    for (int off = 16; off > 0; off >>= 1) {
        s  += __shfl_xor_sync(0xffffffffu, s,  off);
        ss += __shfl_xor_sync(0xffffffffu, ss, off);
    }
    float mean = s * (1.f / DMODEL);
    float var  = ss * (1.f / DMODEL) - mean * mean;
    float rstd = rsqrtf(var + LN_EPS);

    float* o = out + (size_t)row * DMODEL;
#pragma unroll
    for (int i = 0; i < 8; i++) {
        int cc = lane + i * 32;
        o[cc] = (v[i] - mean) * rstd * w[cc] + b[cc];
    }
}

// ---------------------------------------------------------------------------
// Causal depthwise conv (width 4) + SiLU
// ---------------------------------------------------------------------------
__global__ __launch_bounds__(256)
void conv_silu_kernel(const float* __restrict__ xz,
                      const float* __restrict__ cw, const float* __restrict__ cb,
                      float* __restrict__ u)
{
    int idx = blockIdx.x * blockDim.x + threadIdx.x;
    if (idx >= MROWS * DINNER) return;
    int d = idx & (DINNER - 1);
    int t = (idx >> 9) & (SEQ - 1);
    int b = idx >> 18;

    const float* base = xz + (size_t)(b * SEQ) * (2 * DINNER) + d;
    float acc = cb[d];
#pragma unroll
    for (int k = 0; k < DCONV; k++) {
        int tt = t - (DCONV - 1) + k;
        if (tt >= 0) acc += base[(size_t)tt * (2 * DINNER)] * cw[d * DCONV + k];
    }
    u[idx] = acc / (1.f + __expf(-acc));
}

// ---------------------------------------------------------------------------
// Selective scan: thread = (b, d, s). 16-lane shfl reduce over states.
// ---------------------------------------------------------------------------
__global__ __launch_bounds__(256)
void scan_kernel(const float* __restrict__ dt, const float* __restrict__ u,
                 const float* __restrict__ dbl, const float* __restrict__ xz,
                 const float* __restrict__ A_log, const float* __restrict__ Dvec,
                 float* __restrict__ y)
{
    int tid  = blockIdx.x * blockDim.x + threadIdx.x;
    int s    = tid & (DSTATE - 1);
    int pair = tid >> 4;
    int d    = pair & (DINNER - 1);
    int b    = pair >> 9;

    float A  = -__expf(A_log[d * DSTATE + s]);
    float Dp = Dvec[d];
    float h  = 0.f;

    const float* dt_p = dt  + (size_t)b * SEQ * DINNER + d;
    const float* u_p  = u   + (size_t)b * SEQ * DINNER + d;
    const float* bc_p = dbl + (size_t)b * SEQ * 48;
    const float* z_p  = xz  + (size_t)b * SEQ * (2 * DINNER) + DINNER + d;
    float*       y_p  = y   + (size_t)b * SEQ * DINNER + d;

    for (int t = 0; t < SEQ; t++) {
        float dtv = dt_p[(size_t)t * DINNER];
        float uv  = u_p [(size_t)t * DINNER];
        float Bv  = bc_p[t * 48 + DTRANK + s];
        float Cv  = bc_p[t * 48 + DTRANK + DSTATE + s];

        h = __expf(dtv * A) * h + dtv * uv * Bv;
        float yv = h * Cv;
        yv += __shfl_xor_sync(0xffffffffu, yv, 8);
        yv += __shfl_xor_sync(0xffffffffu, yv, 4);
        yv += __shfl_xor_sync(0xffffffffu, yv, 2);
        yv += __shfl_xor_sync(0xffffffffu, yv, 1);

        if (s == 0) {
            float zv  = z_p[(size_t)t * (2 * DINNER)];
            float out = (yv + uv * Dp) * (zv / (1.f + __expf(-zv)));
            y_p[(size_t)t * DINNER] = out;
        }
    }
}

// ---------------------------------------------------------------------------
// Head
// ---------------------------------------------------------------------------
__global__ __launch_bounds__(256)
void head1_kernel(const float* __restrict__ h,
                  const float* __restrict__ w1, const float* __restrict__ b1,
                  float* __restrict__ t1)
{
    __shared__ float hs[DMODEL];
    int b = blockIdx.x;
    int n = threadIdx.x;
    hs[n] = h[((size_t)b * SEQ + (SEQ - 1)) * DMODEL + n];
    __syncthreads();

    const float4* wp = (const float4*)(w1 + (size_t)n * DMODEL);
    float acc = b1[n];
#pragma unroll 8
    for (int k = 0; k < DMODEL / 4; k++) {
        float4 w4 = wp[k];
        acc += hs[4*k+0]*w4.x + hs[4*k+1]*w4.y + hs[4*k+2]*w4.z + hs[4*k+3]*w4.w;
    }
    t1[b * DMODEL + n] = fmaxf(acc, 0.f);
}

__global__ __launch_bounds__(32)
void head2_kernel(const float* __restrict__ t1,
                  const float* __restrict__ w2, const float* __restrict__ b2,
                  float* __restrict__ out)
{
    int b = blockIdx.x;
    int lane = threadIdx.x;
    float acc = 0.f;
#pragma unroll
    for (int k = lane; k < DMODEL; k += 32)
        acc += t1[b * DMODEL + k] * w2[k];
#pragma unroll
    for (int off = 16; off > 0; off >>= 1)
        acc += __shfl_xor_sync(0xffffffffu, acc, off);
    if (lane == 0) out[b] = acc + b2[0];
}

// ---------------------------------------------------------------------------
// Host launcher
// ---------------------------------------------------------------------------
extern "C" void kernel_launch(void* const* d_in, const int* in_sizes, int n_in,
                              void* d_out, int out_size)
{
    const float* x            = (const float*)d_in[0];
    const float* input_proj_w = (const float*)d_in[1];
    const float* input_proj_b = (const float*)d_in[2];
    const float* ln_w         = (const float*)d_in[3];
    const float* ln_b         = (const float*)d_in[4];
    const float* in_proj_w    = (const float*)d_in[5];
    const float* conv_w       = (const float*)d_in[6];
    const float* conv_b       = (const float*)d_in[7];
    const float* x_proj_w     = (const float*)d_in[8];
    const float* dt_proj_w    = (const float*)d_in[9];
    const float* dt_proj_b    = (const float*)d_in[10];
    const float* A_log        = (const float*)d_in[11];
    const float* Dvec         = (const float*)d_in[12];
    const float* out_proj_w   = (const float*)d_in[13];
    const float* head_w1      = (const float*)d_in[14];
    const float* head_b1      = (const float*)d_in[15];
    const float* head_w2      = (const float*)d_in[16];
    const float* head_b2      = (const float*)d_in[17];
    float* out = (float*)d_out;

    float *p_h, *p_xn, *p_xz, *p_u, *p_dbl, *p_dt, *p_y, *p_t1, *p_part;
    cudaGetSymbolAddress((void**)&p_h,    g_h);
    cudaGetSymbolAddress((void**)&p_xn,   g_xn);
    cudaGetSymbolAddress((void**)&p_xz,   g_xz);
    cudaGetSymbolAddress((void**)&p_u,    g_u);
    cudaGetSymbolAddress((void**)&p_dbl,  g_dbl);
    cudaGetSymbolAddress((void**)&p_dt,   g_dt);
    cudaGetSymbolAddress((void**)&p_y,    g_y);
    cudaGetSymbolAddress((void**)&p_t1,   g_t1);
    cudaGetSymbolAddress((void**)&p_part, g_part);

    // input projection: h = x @ W^T + b  (N=256, K=32) grid (2,32)
    gemm_f2<<<dim3(DMODEL/GBN, MROWS/GBM, 1), 256>>>(
        x, INPUT_DIM, input_proj_w, INPUT_DIM, input_proj_b,
        p_h, DMODEL, 0, DMODEL, INPUT_DIM, 0);

    for (int l = 0; l < NLAYERS; l++) {
        // 1. layernorm
        ln_kernel<<<MROWS / 8, 256>>>(p_h, ln_w + l * DMODEL, ln_b + l * DMODEL, p_xn);

        // 2. in_proj: xz = xn @ W^T  (N=1024, K=256) grid (8,32) = 256 CTAs
        gemm_f2<<<dim3((2*DINNER)/GBN, MROWS/GBM, 1), 256>>>(
            p_xn, DMODEL, in_proj_w + (size_t)l * 2 * DINNER * DMODEL, DMODEL,
            nullptr, p_xz, 2 * DINNER, 0, 2 * DINNER, DMODEL, 0);

        // 3. conv + silu -> u
        conv_silu_kernel<<<(MROWS * DINNER) / 256, 256>>>(
            p_xz, conv_w + l * DINNER * DCONV, conv_b + l * DINNER, p_u);

        // 4. x_proj: dbl = u @ W^T  (N=48, K=512), split-K=4 -> 128 CTAs
        gemm_f2<<<dim3(1, MROWS/GBM, 4), 256>>>(
            p_u, DINNER, x_proj_w + (size_t)l * 48 * DINNER, DINNER,
            nullptr, p_part, 48, (size_t)MROWS * 48, 48, DINNER / 4, 0);
        reduce_kernel<<<(MROWS * 48) / 1024, 256>>>(
            p_part, (size_t)MROWS * 48, 4, nullptr, p_dbl, MROWS * 48);

        // 5. dt = softplus(dbl[:, :16] @ dt_proj_w^T + b)  (N=512, K=16) grid (4,32)
        gemm_f2<<<dim3(DINNER/GBN, MROWS/GBM, 1), 256>>>(
            p_dbl, 48, dt_proj_w + (size_t)l * DINNER * DTRANK, DTRANK,
            dt_proj_b + l * DINNER, p_dt, DINNER, 0, DINNER, DTRANK, 1);

        // 6. selective scan
        scan_kernel<<<(MROWS * DSTATE) / 256, 256>>>(
            p_dt, p_u, p_dbl, p_xz,
            A_log + (size_t)l * DINNER * DSTATE, Dvec + l * DINNER, p_y);

        // 7. out_proj: h += y @ W^T  (N=256, K=512), split-K=2, resid in reduce
        gemm_f2<<<dim3(DMODEL/GBN, MROWS/GBM, 2), 256>>>(
            p_y, DINNER, out_proj_w + (size_t)l * DMODEL * DINNER, DINNER,
            nullptr, p_part, DMODEL, (size_t)MROWS * DMODEL, DMODEL, DINNER / 2, 0);
        reduce_kernel<<<(MROWS * DMODEL) / 1024, 256>>>(
            p_part, (size_t)MROWS * DMODEL, 2, p_h, p_h, MROWS * DMODEL);
    }

    // head
    head1_kernel<<<BATCH, DMODEL>>>(p_h, head_w1, head_b1, p_t1);
    head2_kernel<<<BATCH, 32>>>(p_t1, head_w2, head_b2, out);
}

// round 7
// speedup vs baseline: 1.2510x; 1.2510x over previous
#include <cuda_runtime.h>
#include <cuda_bf16.h>
#include <cstdint>

// ---------------------------------------------------------------------------
// Model constants
// ---------------------------------------------------------------------------
#define BATCH     8
#define SEQ       512
#define INPUT_DIM 32
#define DMODEL    256
#define NLAYERS   4
#define DSTATE    16
#define DCONV     4
#define DINNER    512
#define DTRANK    16
#define MROWS     (BATCH*SEQ)    // 4096
#define LN_EPS    1e-5f

// ---------------------------------------------------------------------------
// Device scratch
// ---------------------------------------------------------------------------
__device__ float g_h   [MROWS * DMODEL];
__device__ float g_xn  [MROWS * DMODEL];
__device__ float g_xz  [MROWS * 2 * DINNER];
__device__ float g_u   [MROWS * DINNER];
__device__ float g_dbl [MROWS * 48];
__device__ float g_dt  [MROWS * DINNER];
__device__ float g_y   [MROWS * DINNER];
__device__ float g_t1  [BATCH * DMODEL];
__device__ float g_part[2 * MROWS * DMODEL];   // split-K partials

// ---------------------------------------------------------------------------
// PTX helpers
// ---------------------------------------------------------------------------
__device__ __forceinline__ uint32_t f2tf32(float f) {
    uint32_t u;
    asm("cvt.rna.tf32.f32 %0, %1;" : "=r"(u) : "f"(f));
    return u;
}

__device__ __forceinline__ void mma_tf32(float* cc, const uint32_t* a, const uint32_t* b) {
    asm volatile("mma.sync.aligned.m16n8k8.row.col.f32.tf32.tf32.f32 "
                 "{%0,%1,%2,%3}, {%4,%5,%6,%7}, {%8,%9}, {%0,%1,%2,%3};"
                 : "+f"(cc[0]), "+f"(cc[1]), "+f"(cc[2]), "+f"(cc[3])
                 : "r"(a[0]), "r"(a[1]), "r"(a[2]), "r"(a[3]),
                   "r"(b[0]), "r"(b[1]));
}

__device__ __forceinline__ uint32_t smem_u32(const void* p) {
    uint32_t a;
    asm("{ .reg .u64 t; cvta.to.shared.u64 t, %1; cvt.u32.u64 %0, t; }"
        : "=r"(a) : "l"(p));
    return a;
}

__device__ __forceinline__ void cpasync16(uint32_t dst, const void* src, int src_sz) {
    asm volatile("cp.async.cg.shared.global [%0], [%1], 16, %2;"
                 :: "r"(dst), "l"(src), "r"(src_sz) : "memory");
}
#define CP_COMMIT()  asm volatile("cp.async.commit_group;" ::: "memory")
#define CP_WAIT(n)   asm volatile("cp.async.wait_group %0;" :: "n"(n) : "memory")

// ---------------------------------------------------------------------------
// tf32 mma.sync NT GEMM, cp.async double buffer (static 40KB SMEM).
//   C[m,n] = sum_k A[m,k] * W[n,k]   (+bias, +resid, act)
// CTA 128x128, BK=16, 256 threads (8 warps, warp tile 32x64).
// Stage: A 128x20 + B 128x20 floats (stride 20 -> conflict-free frag loads).
// Split-K via blockIdx.z (k-slice z*Klen.., C += z*zstride).
// Requirements: M%128==0, Klen%16==0, N%8==0.
// act: 0 none, 1 softplus
// ---------------------------------------------------------------------------
#define BM 128
#define BN 128
#define BK 16
#define SLD 20
#define STAGE_F (BM * SLD)     // 2560 floats per tile per stage

__global__ __launch_bounds__(256)
void gemm_mma(const float* __restrict__ A, int lda,
              const float* __restrict__ W, int ldw,
              const float* __restrict__ bias,
              const float* __restrict__ resid,
              float* __restrict__ C, int ldc, size_t zstride,
              int N, int Klen, int act)
{
    __shared__ float Asm[2][STAGE_F];
    __shared__ float Bsm[2][STAGE_F];

    const int tid  = threadIdx.x;
    const int wid  = tid >> 5;
    const int lane = tid & 31;
    const int wm   = wid & 3;                 // 4 warps in M
    const int wn   = wid >> 2;                // 2 warps in N
    const int g    = lane >> 2;               // 0..7
    const int c    = lane & 3;                // 0..3
    const int m0   = wm * 32;
    const int n0   = wn * 64;

    const int row0 = blockIdx.y * BM;
    const int col0 = blockIdx.x * BN;
    const int kofs = blockIdx.z * Klen;
    C += (size_t)blockIdx.z * zstride;

    // cp.async mapping: row = tid>>1 (0..127), k-half = (tid&1)*8 floats
    const int cr  = tid >> 1;
    const int ckq = (tid & 1) * 8;
    const int bvalid = (col0 + cr) < N ? 16 : 0;

    const uint32_t smA = smem_u32(Asm);
    const uint32_t smB = smem_u32(Bsm);
    const int T = Klen / BK;

    auto issue = [&](int t) {
        if (t < T) {
            const float* Ap = A + (size_t)(row0 + cr) * lda + kofs + t * BK + ckq;
            uint32_t da = smA + (((t & 1) * STAGE_F) + cr * SLD + ckq) * 4;
            cpasync16(da,      Ap,     16);
            cpasync16(da + 16, Ap + 4, 16);
            const float* Wp = W + (size_t)(col0 + cr) * ldw + kofs + t * BK + ckq;
            uint32_t db = smB + (((t & 1) * STAGE_F) + cr * SLD + ckq) * 4;
            cpasync16(db,      Wp,     bvalid);
            cpasync16(db + 16, Wp + 4, bvalid);
        }
    };

    issue(0); CP_COMMIT();

    float acc[2][8][4];
#pragma unroll
    for (int mi = 0; mi < 2; mi++)
#pragma unroll
        for (int ni = 0; ni < 8; ni++)
#pragma unroll
            for (int e = 0; e < 4; e++) acc[mi][ni][e] = 0.f;

    for (int t = 0; t < T; t++) {
        issue(t + 1);
        CP_COMMIT();                 // commit even when empty: stable group count
        CP_WAIT(1);                  // stage t complete; t+1 may be in flight
        __syncthreads();

        const float* As = Asm[t & 1];
        const float* Bs = Bsm[t & 1];

#pragma unroll
        for (int kb = 0; kb < BK; kb += 8) {
            uint32_t a[2][4], b[8][2];
#pragma unroll
            for (int mi = 0; mi < 2; mi++) {
                const int r = m0 + mi * 16 + g;
                a[mi][0] = f2tf32(As[(r    ) * SLD + kb + c]);
                a[mi][1] = f2tf32(As[(r + 8) * SLD + kb + c]);
                a[mi][2] = f2tf32(As[(r    ) * SLD + kb + c + 4]);
                a[mi][3] = f2tf32(As[(r + 8) * SLD + kb + c + 4]);
            }
#pragma unroll
            for (int ni = 0; ni < 8; ni++) {
                const int r = n0 + ni * 8 + g;
                b[ni][0] = f2tf32(Bs[r * SLD + kb + c]);
                b[ni][1] = f2tf32(Bs[r * SLD + kb + c + 4]);
            }
#pragma unroll
            for (int mi = 0; mi < 2; mi++)
#pragma unroll
                for (int ni = 0; ni < 8; ni++)
                    mma_tf32(acc[mi][ni], a[mi], b[ni]);
        }
        __syncthreads();   // readers of stage t done before issue(t+2) overwrites it
    }

    // ---- epilogue ----
#pragma unroll
    for (int mi = 0; mi < 2; mi++) {
#pragma unroll
        for (int ni = 0; ni < 8; ni++) {
            const int colb = col0 + n0 + ni * 8;
            if (colb < N) {
                const int cc = colb + c * 2;
#pragma unroll
                for (int half = 0; half < 2; half++) {
                    const int r = row0 + m0 + mi * 16 + g + half * 8;
                    float2 v = make_float2(acc[mi][ni][half * 2],
                                           acc[mi][ni][half * 2 + 1]);
                    if (bias)  { v.x += bias[cc];  v.y += bias[cc + 1]; }
                    if (resid) {
                        const float* rp = resid + (size_t)r * ldc + cc;
                        v.x += rp[0]; v.y += rp[1];
                    }
                    if (act == 1) {
                        v.x = (v.x > 20.f) ? v.x : log1pf(__expf(v.x));
                        v.y = (v.y > 20.f) ? v.y : log1pf(__expf(v.y));
                    }
                    *(float2*)(C + (size_t)r * ldc + cc) = v;
                }
            }
        }
    }
}

// ---------------------------------------------------------------------------
// Split-K reduce: out[i] = (resid?resid[i]:0) + sum_z part[z*zstride + i]
// ---------------------------------------------------------------------------
__global__ __launch_bounds__(256)
void reduce_kernel(const float* __restrict__ part, size_t zstride, int nz,
                   const float* __restrict__ resid,
                   float* __restrict__ out, int n)
{
    int i = (blockIdx.x * blockDim.x + threadIdx.x) * 4;
    if (i >= n) return;
    float4 s = resid ? *(const float4*)(resid + i) : make_float4(0.f,0.f,0.f,0.f);
    for (int zi = 0; zi < nz; zi++) {
        float4 p = *(const float4*)(part + (size_t)zi * zstride + i);
        s.x += p.x; s.y += p.y; s.z += p.z; s.w += p.w;
    }
    *(float4*)(out + i) = s;
}

// ---------------------------------------------------------------------------
// LayerNorm: one warp per row of 256
// ---------------------------------------------------------------------------
__global__ __launch_bounds__(256)
void ln_kernel(const float* __restrict__ h,
               const float* __restrict__ w, const float* __restrict__ b,
               float* __restrict__ out)
{
    int row  = blockIdx.x * 8 + (threadIdx.x >> 5);
    int lane = threadIdx.x & 31;
    const float* x = h + (size_t)row * DMODEL;

    float v[8];
    float s = 0.f, ss = 0.f;
#pragma unroll
    for (int i = 0; i < 8; i++) {
        v[i] = x[lane + i * 32];
        s  += v[i];
        ss += v[i] * v[i];
    }
#pragma unroll
    for (int off = 16; off > 0; off >>= 1) {
        s  += __shfl_xor_sync(0xffffffffu, s,  off);
        ss += __shfl_xor_sync(0xffffffffu, ss, off);
    }
    float mean = s * (1.f / DMODEL);
    float var  = ss * (1.f / DMODEL) - mean * mean;
    float rstd = rsqrtf(var + LN_EPS);

    float* o = out + (size_t)row * DMODEL;
#pragma unroll
    for (int i = 0; i < 8; i++) {
        int cc = lane + i * 32;
        o[cc] = (v[i] - mean) * rstd * w[cc] + b[cc];
    }
}

// ---------------------------------------------------------------------------
// Causal depthwise conv (width 4) + SiLU
// ---------------------------------------------------------------------------
__global__ __launch_bounds__(256)
void conv_silu_kernel(const float* __restrict__ xz,
                      const float* __restrict__ cw, const float* __restrict__ cb,
                      float* __restrict__ u)
{
    int idx = blockIdx.x * blockDim.x + threadIdx.x;
    if (idx >= MROWS * DINNER) return;
    int d = idx & (DINNER - 1);
    int t = (idx >> 9) & (SEQ - 1);
    int b = idx >> 18;

    const float* base = xz + (size_t)(b * SEQ) * (2 * DINNER) + d;
    float acc = cb[d];
#pragma unroll
    for (int k = 0; k < DCONV; k++) {
        int tt = t - (DCONV - 1) + k;
        if (tt >= 0) acc += base[(size_t)tt * (2 * DINNER)] * cw[d * DCONV + k];
    }
    u[idx] = acc / (1.f + __expf(-acc));
}

// ---------------------------------------------------------------------------
// Selective scan: thread = (b, d, s). 16-lane shfl reduce over states.
// ---------------------------------------------------------------------------
__global__ __launch_bounds__(256)
void scan_kernel(const float* __restrict__ dt, const float* __restrict__ u,
                 const float* __restrict__ dbl, const float* __restrict__ xz,
                 const float* __restrict__ A_log, const float* __restrict__ Dvec,
                 float* __restrict__ y)
{
    int tid  = blockIdx.x * blockDim.x + threadIdx.x;
    int s    = tid & (DSTATE - 1);
    int pair = tid >> 4;
    int d    = pair & (DINNER - 1);
    int b    = pair >> 9;

    float A  = -__expf(A_log[d * DSTATE + s]);
    float Dp = Dvec[d];
    float h  = 0.f;

    const float* dt_p = dt  + (size_t)b * SEQ * DINNER + d;
    const float* u_p  = u   + (size_t)b * SEQ * DINNER + d;
    const float* bc_p = dbl + (size_t)b * SEQ * 48;
    const float* z_p  = xz  + (size_t)b * SEQ * (2 * DINNER) + DINNER + d;
    float*       y_p  = y   + (size_t)b * SEQ * DINNER + d;

    for (int t = 0; t < SEQ; t++) {
        float dtv = dt_p[(size_t)t * DINNER];
        float uv  = u_p [(size_t)t * DINNER];
        float Bv  = bc_p[t * 48 + DTRANK + s];
        float Cv  = bc_p[t * 48 + DTRANK + DSTATE + s];

        h = __expf(dtv * A) * h + dtv * uv * Bv;
        float yv = h * Cv;
        yv += __shfl_xor_sync(0xffffffffu, yv, 8);
        yv += __shfl_xor_sync(0xffffffffu, yv, 4);
        yv += __shfl_xor_sync(0xffffffffu, yv, 2);
        yv += __shfl_xor_sync(0xffffffffu, yv, 1);

        if (s == 0) {
            float zv  = z_p[(size_t)t * (2 * DINNER)];
            float out = (yv + uv * Dp) * (zv / (1.f + __expf(-zv)));
            y_p[(size_t)t * DINNER] = out;
        }
    }
}

// ---------------------------------------------------------------------------
// Head
// ---------------------------------------------------------------------------
__global__ __launch_bounds__(256)
void head1_kernel(const float* __restrict__ h,
                  const float* __restrict__ w1, const float* __restrict__ b1,
                  float* __restrict__ t1)
{
    __shared__ float hs[DMODEL];
    int b = blockIdx.x;
    int n = threadIdx.x;
    hs[n] = h[((size_t)b * SEQ + (SEQ - 1)) * DMODEL + n];
    __syncthreads();

    const float4* wp = (const float4*)(w1 + (size_t)n * DMODEL);
    float acc = b1[n];
#pragma unroll 8
    for (int k = 0; k < DMODEL / 4; k++) {
        float4 w4 = wp[k];
        acc += hs[4*k+0]*w4.x + hs[4*k+1]*w4.y + hs[4*k+2]*w4.z + hs[4*k+3]*w4.w;
    }
    t1[b * DMODEL + n] = fmaxf(acc, 0.f);
}

__global__ __launch_bounds__(32)
void head2_kernel(const float* __restrict__ t1,
                  const float* __restrict__ w2, const float* __restrict__ b2,
                  float* __restrict__ out)
{
    int b = blockIdx.x;
    int lane = threadIdx.x;
    float acc = 0.f;
#pragma unroll
    for (int k = lane; k < DMODEL; k += 32)
        acc += t1[b * DMODEL + k] * w2[k];
#pragma unroll
    for (int off = 16; off > 0; off >>= 1)
        acc += __shfl_xor_sync(0xffffffffu, acc, off);
    if (lane == 0) out[b] = acc + b2[0];
}

// ---------------------------------------------------------------------------
// Host launcher
// ---------------------------------------------------------------------------
extern "C" void kernel_launch(void* const* d_in, const int* in_sizes, int n_in,
                              void* d_out, int out_size)
{
    const float* x            = (const float*)d_in[0];
    const float* input_proj_w = (const float*)d_in[1];
    const float* input_proj_b = (const float*)d_in[2];
    const float* ln_w         = (const float*)d_in[3];
    const float* ln_b         = (const float*)d_in[4];
    const float* in_proj_w    = (const float*)d_in[5];
    const float* conv_w       = (const float*)d_in[6];
    const float* conv_b       = (const float*)d_in[7];
    const float* x_proj_w     = (const float*)d_in[8];
    const float* dt_proj_w    = (const float*)d_in[9];
    const float* dt_proj_b    = (const float*)d_in[10];
    const float* A_log        = (const float*)d_in[11];
    const float* Dvec         = (const float*)d_in[12];
    const float* out_proj_w   = (const float*)d_in[13];
    const float* head_w1      = (const float*)d_in[14];
    const float* head_b1      = (const float*)d_in[15];
    const float* head_w2      = (const float*)d_in[16];
    const float* head_b2      = (const float*)d_in[17];
    float* out = (float*)d_out;

    float *p_h, *p_xn, *p_xz, *p_u, *p_dbl, *p_dt, *p_y, *p_t1, *p_part;
    cudaGetSymbolAddress((void**)&p_h,    g_h);
    cudaGetSymbolAddress((void**)&p_xn,   g_xn);
    cudaGetSymbolAddress((void**)&p_xz,   g_xz);
    cudaGetSymbolAddress((void**)&p_u,    g_u);
    cudaGetSymbolAddress((void**)&p_dbl,  g_dbl);
    cudaGetSymbolAddress((void**)&p_dt,   g_dt);
    cudaGetSymbolAddress((void**)&p_y,    g_y);
    cudaGetSymbolAddress((void**)&p_t1,   g_t1);
    cudaGetSymbolAddress((void**)&p_part, g_part);

    // input projection: h = x @ W^T + b  (N=256, K=32) grid (2,32)
    gemm_mma<<<dim3(DMODEL/BN, MROWS/BM, 1), 256>>>(
        x, INPUT_DIM, input_proj_w, INPUT_DIM, input_proj_b, nullptr,
        p_h, DMODEL, 0, DMODEL, INPUT_DIM, 0);

    for (int l = 0; l < NLAYERS; l++) {
        // 1. layernorm
        ln_kernel<<<MROWS / 8, 256>>>(p_h, ln_w + l * DMODEL, ln_b + l * DMODEL, p_xn);

        // 2. in_proj: xz = xn @ W^T  (N=1024, K=256) grid (8,32) = 256 CTAs
        gemm_mma<<<dim3((2*DINNER)/BN, MROWS/BM, 1), 256>>>(
            p_xn, DMODEL, in_proj_w + (size_t)l * 2 * DINNER * DMODEL, DMODEL,
            nullptr, nullptr, p_xz, 2 * DINNER, 0, 2 * DINNER, DMODEL, 0);

        // 3. conv + silu -> u
        conv_silu_kernel<<<(MROWS * DINNER) / 256, 256>>>(
            p_xz, conv_w + l * DINNER * DCONV, conv_b + l * DINNER, p_u);

        // 4. x_proj: dbl = u @ W^T  (N=48, K=512), split-K=4 -> 128 CTAs
        gemm_mma<<<dim3(1, MROWS/BM, 4), 256>>>(
            p_u, DINNER, x_proj_w + (size_t)l * 48 * DINNER, DINNER,
            nullptr, nullptr, p_part, 48, (size_t)MROWS * 48, 48, DINNER / 4, 0);
        reduce_kernel<<<(MROWS * 48) / 1024, 256>>>(
            p_part, (size_t)MROWS * 48, 4, nullptr, p_dbl, MROWS * 48);

        // 5. dt = softplus(dbl[:, :16] @ dt_proj_w^T + b)  (N=512, K=16) grid (4,32)
        gemm_mma<<<dim3(DINNER/BN, MROWS/BM, 1), 256>>>(
            p_dbl, 48, dt_proj_w + (size_t)l * DINNER * DTRANK, DTRANK,
            dt_proj_b + l * DINNER, nullptr, p_dt, DINNER, 0, DINNER, DTRANK, 1);

        // 6. selective scan
        scan_kernel<<<(MROWS * DSTATE) / 256, 256>>>(
            p_dt, p_u, p_dbl, p_xz,
            A_log + (size_t)l * DINNER * DSTATE, Dvec + l * DINNER, p_y);

        // 7. out_proj: h += y @ W^T  (N=256, K=512), split-K=2, resid in reduce
        gemm_mma<<<dim3(DMODEL/BN, MROWS/BM, 2), 256>>>(
            p_y, DINNER, out_proj_w + (size_t)l * DMODEL * DINNER, DINNER,
            nullptr, nullptr, p_part, DMODEL, (size_t)MROWS * DMODEL, DMODEL, DINNER / 2, 0);
        reduce_kernel<<<(MROWS * DMODEL) / 1024, 256>>>(
            p_part, (size_t)MROWS * DMODEL, 2, p_h, p_h, MROWS * DMODEL);
    }

    // head
    head1_kernel<<<BATCH, DMODEL>>>(p_h, head_w1, head_b1, p_t1);
    head2_kernel<<<BATCH, 32>>>(p_t1, head_w2, head_b2, out);
}